// round 4
// baseline (speedup 1.0000x reference)
#include <cuda_runtime.h>

#define BATCH 16384
#define STEPS 200
#define LR 0.01f
#define HID 64
#define PROJ 8
#define SPEC 40
#define TPB 128

// Scratch for the precomputed A = (W2 @ R^T) @ R[:, :6]  -> [HID][6]
__device__ float g_A[HID * 6];

// ---------------------------------------------------------------------------
// Prologue: compute A[k][i] = sum_p ( sum_j W2[k,j]*R[p,j] ) * R[p,i]
// Single block of HID threads; negligible cost.
// ---------------------------------------------------------------------------
__global__ void compute_A_kernel(const float* __restrict__ W2,
                                 const float* __restrict__ R) {
    int k = threadIdx.x;
    if (k >= HID) return;
    float wr[PROJ];
#pragma unroll
    for (int p = 0; p < PROJ; p++) {
        float s = 0.f;
#pragma unroll
        for (int j = 0; j < SPEC; j++)
            s = fmaf(W2[k * SPEC + j], R[p * SPEC + j], s);
        wr[p] = s;
    }
#pragma unroll
    for (int i = 0; i < 6; i++) {
        float s = 0.f;
#pragma unroll
        for (int p = 0; p < PROJ; p++)
            s = fmaf(wr[p], R[p * SPEC + i], s);
        g_A[k * 6 + i] = s;
    }
}

// ---------------------------------------------------------------------------
// Main solver: one thread per spectrum row, 200 iterations.
// Per step: pre_k = b1_k + sum_i u_i*W1[i,k]; h = tanh(pre);
//           grad6 = h @ A + c;  u = clip(u - LR*grad6, 0, 1)
// W1/b1 and A live in shared as packed float4 pairs (4x LDS.128 per k,
// uniform address -> conflict-free broadcast).
// ---------------------------------------------------------------------------
__global__ __launch_bounds__(TPB, 1)
void solve_kernel(const float* __restrict__ spec,
                  const float* __restrict__ W1,
                  const float* __restrict__ b1,
                  const float* __restrict__ b2,
                  const float* __restrict__ R,
                  float* __restrict__ out) {
    __shared__ float4 sW[HID][2];   // {w0..w3}, {w4,w5,b1,0}
    __shared__ float4 sA[HID][2];   // {a0..a3}, {a4,a5,0,0}
    __shared__ float  sR[PROJ * SPEC];
    __shared__ float  sB2[SPEC];

    const int tid = threadIdx.x;

    if (tid < HID) {
        int k = tid;
        sW[k][0] = make_float4(W1[0 * HID + k], W1[1 * HID + k],
                               W1[2 * HID + k], W1[3 * HID + k]);
        sW[k][1] = make_float4(W1[4 * HID + k], W1[5 * HID + k],
                               b1[k], 0.f);
        sA[k][0] = make_float4(g_A[k * 6 + 0], g_A[k * 6 + 1],
                               g_A[k * 6 + 2], g_A[k * 6 + 3]);
        sA[k][1] = make_float4(g_A[k * 6 + 4], g_A[k * 6 + 5], 0.f, 0.f);
    }
    for (int idx = tid; idx < PROJ * SPEC; idx += TPB) sR[idx] = R[idx];
    if (tid < SPEC) sB2[tid] = b2[tid];
    __syncthreads();

    const int row = blockIdx.x * TPB + tid;

    // Per-row constant: c = R[:, :6]^T @ ( R @ (b2 - spec_row) )
    float z[PROJ];
#pragma unroll
    for (int p = 0; p < PROJ; p++) z[p] = 0.f;
    const float* srow = spec + (size_t)row * SPEC;
#pragma unroll 8
    for (int j = 0; j < SPEC; j++) {
        float d = sB2[j] - srow[j];
#pragma unroll
        for (int p = 0; p < PROJ; p++)
            z[p] = fmaf(sR[p * SPEC + j], d, z[p]);
    }
    float c0 = 0.f, c1 = 0.f, c2 = 0.f, c3 = 0.f, c4 = 0.f, c5 = 0.f;
#pragma unroll
    for (int p = 0; p < PROJ; p++) {
        c0 = fmaf(sR[p * SPEC + 0], z[p], c0);
        c1 = fmaf(sR[p * SPEC + 1], z[p], c1);
        c2 = fmaf(sR[p * SPEC + 2], z[p], c2);
        c3 = fmaf(sR[p * SPEC + 3], z[p], c3);
        c4 = fmaf(sR[p * SPEC + 4], z[p], c4);
        c5 = fmaf(sR[p * SPEC + 5], z[p], c5);
    }

    float u0 = 0.5f, u1 = 0.5f, u2 = 0.5f, u3 = 0.5f, u4 = 0.5f, u5 = 0.5f;

    for (int t = 0; t < STEPS; t++) {
        float g0 = c0, g1 = c1, g2 = c2, g3 = c3, g4 = c4, g5 = c5;
#pragma unroll 8
        for (int k = 0; k < HID; k++) {
            const float4 wA = sW[k][0];
            const float4 wB = sW[k][1];
            float pre = wB.z;
            pre = fmaf(u0, wA.x, pre);
            pre = fmaf(u1, wA.y, pre);
            pre = fmaf(u2, wA.z, pre);
            pre = fmaf(u3, wA.w, pre);
            pre = fmaf(u4, wB.x, pre);
            pre = fmaf(u5, wB.y, pre);
            // accurate tanh: 1 - 2/(exp(2x)+1)   (exp via MUFU.EX2, ~1e-7 err)
            float e = __expf(pre + pre);
            float h = 1.f - __fdividef(2.f, e + 1.f);
            const float4 aA = sA[k][0];
            const float4 aB = sA[k][1];
            g0 = fmaf(h, aA.x, g0);
            g1 = fmaf(h, aA.y, g1);
            g2 = fmaf(h, aA.z, g2);
            g3 = fmaf(h, aA.w, g3);
            g4 = fmaf(h, aB.x, g4);
            g5 = fmaf(h, aB.y, g5);
        }
        u0 = fminf(fmaxf(fmaf(-LR, g0, u0), 0.f), 1.f);
        u1 = fminf(fmaxf(fmaf(-LR, g1, u1), 0.f), 1.f);
        u2 = fminf(fmaxf(fmaf(-LR, g2, u2), 0.f), 1.f);
        u3 = fminf(fmaxf(fmaf(-LR, g3, u3), 0.f), 1.f);
        u4 = fminf(fmaxf(fmaf(-LR, g4, u4), 0.f), 1.f);
        u5 = fminf(fmaxf(fmaf(-LR, g5, u5), 0.f), 1.f);
    }

    float* orow = out + (size_t)row * 6;
    orow[0] = u0; orow[1] = u1; orow[2] = u2;
    orow[3] = u3; orow[4] = u4; orow[5] = u5;
}

// ---------------------------------------------------------------------------
// Inputs (metadata order): spectrum, W1, b1, W2, b2, R.  Output: (BATCH, 6) f32
// ---------------------------------------------------------------------------
extern "C" void kernel_launch(void* const* d_in, const int* in_sizes, int n_in,
                              void* d_out, int out_size) {
    const float* spec = (const float*)d_in[0];
    const float* W1   = (const float*)d_in[1];
    const float* b1   = (const float*)d_in[2];
    const float* W2   = (const float*)d_in[3];
    const float* b2   = (const float*)d_in[4];
    const float* R    = (const float*)d_in[5];
    float* out = (float*)d_out;

    compute_A_kernel<<<1, HID>>>(W2, R);
    solve_kernel<<<BATCH / TPB, TPB>>>(spec, W1, b1, b2, R, out);
}